// round 6
// baseline (speedup 1.0000x reference)
#include <cuda_runtime.h>
#include <cstdint>

// out[c,t,x,y] = mc ? k[t] : mp ? 0.5*k[t-1] : mn ? 0.25*k[t+1] : 0   (cases exclusive)
// Mask is channel-invariant -> precompute 2-bit selector per (t, xy) into a
// 1 MB L2-resident word-major table sel[word][g]; word w packs t = 4w..4w+3
// (4 lanes * 2 bits per t). Main kernel: pure 1-load/1-store rolling stream,
// launched with PDL so its launch+prologue overlaps pre's drain.

#define ALPHA 0.5f
#define BETA  0.25f

constexpr int NC = 32;
constexpr int NT = 64;
constexpr int PLANE4 = 256 * 256 / 4;     // 16384 float4 groups per t-slice
constexpr int COLS   = NC * PLANE4;       // 524288 threads in main kernel
constexpr int NWORDS = NT / 4;            // 16 selector words per g

__device__ uint32_t g_sel[NWORDS * PLANE4];   // [word][g], 1 MB

__device__ __forceinline__ uint32_t code1(int mc, int mp, int mn) {
    return mc ? 1u : (mp ? 2u : (mn ? 3u : 0u));
}

// One thread per (word w, g): computes 4 t-steps (t = 4w..4w+3).
// Reads mask[4w-1 .. 4w+4] (6 coalesced int4 loads), writes 1 coalesced word.
__global__ void __launch_bounds__(256)
pre_kernel(const int4* __restrict__ mask)
{
    const int tidg = blockIdx.x * blockDim.x + threadIdx.x;  // 0 .. NWORDS*PLANE4-1
    const int g = tidg & (PLANE4 - 1);
    const int w = tidg >> 14;            // 0..15
    const int t0 = w * 4;

    int4 mbuf[6];
    #pragma unroll
    for (int i = 0; i < 6; i++) {
        const int t = t0 - 1 + i;
        mbuf[i] = (t >= 0 && t < NT) ? __ldg(&mask[t * PLANE4 + g])
                                     : make_int4(0, 0, 0, 0);
    }

    uint32_t word = 0u;
    #pragma unroll
    for (int i = 0; i < 4; i++) {
        const int4 mp = mbuf[i];
        const int4 mc = mbuf[i + 1];
        const int4 mn = mbuf[i + 2];
        uint32_t byte =  code1(mc.x, mp.x, mn.x)
                      | (code1(mc.y, mp.y, mn.y) << 2)
                      | (code1(mc.z, mp.z, mn.z) << 4)
                      | (code1(mc.w, mp.w, mn.w) << 6);
        word |= byte << (i * 8);
    }

    g_sel[w * PLANE4 + g] = word;        // fully coalesced 4B stores

#if __CUDA_ARCH__ >= 900
    cudaTriggerProgrammaticLaunchCompletion();
#endif
}

__device__ __forceinline__ float pick(uint32_t c, float kc, float kp, float kn) {
    return (c == 1u) ? kc
         : (c == 2u) ? ALPHA * kp
         : (c == 3u) ? BETA * kn
         : 0.0f;
}

__global__ void __launch_bounds__(256, 8)
dsb_kernel(const float4* __restrict__ k, float4* __restrict__ out)
{
    const int gid = blockIdx.x * blockDim.x + threadIdx.x;
    const int g = gid & (PLANE4 - 1);
    const int c = gid >> 14;

    const float4* kk = k   + (size_t)c * NT * PLANE4 + g;
    float4*       oo = out + (size_t)c * NT * PLANE4 + g;

    // Prologue: independent of g_sel — overlaps with pre's completion.
    float4 kp = make_float4(0.f, 0.f, 0.f, 0.f);
    float4 kc = __ldcs(kk);

#if __CUDA_ARCH__ >= 900
    cudaGridDependencySynchronize();     // pre's g_sel writes now visible
#endif

    int t = 0;
    #pragma unroll 1
    for (int w = 0; w < NWORDS; w++) {
        const uint32_t wrd = __ldg(&g_sel[w * PLANE4 + g]);   // L2-resident
        #pragma unroll
        for (int tt = 0; tt < 4; tt++) {
            float4 kn = (t < NT - 1) ? __ldcs(kk + (t + 1) * PLANE4)
                                     : make_float4(0.f, 0.f, 0.f, 0.f);

            const uint32_t byte = (wrd >> (tt * 8)) & 0xFFu;
            float4 o;
            o.x = pick( byte       & 3u, kc.x, kp.x, kn.x);
            o.y = pick((byte >> 2) & 3u, kc.y, kp.y, kn.y);
            o.z = pick((byte >> 4) & 3u, kc.z, kp.z, kn.z);
            o.w = pick((byte >> 6) & 3u, kc.w, kp.w, kn.w);

            __stcs(oo + t * PLANE4, o);

            kp = kc; kc = kn;
            t++;
        }
    }
}

extern "C" void kernel_launch(void* const* d_in, const int* in_sizes, int n_in,
                              void* d_out, int out_size)
{
    const float4* k    = (const float4*)d_in[0];
    const int4*   mask = (const int4*)d_in[1];
    float4*       out  = (float4*)d_out;

    pre_kernel<<<(NWORDS * PLANE4) / 256, 256>>>(mask);

    // PDL launch: dsb's grid launch + prologue overlap pre's drain.
    cudaLaunchConfig_t cfg = {};
    cfg.gridDim  = dim3(COLS / 256);
    cfg.blockDim = dim3(256);
    cfg.dynamicSmemBytes = 0;
    cfg.stream = 0;
    cudaLaunchAttribute attr[1];
    attr[0].id = cudaLaunchAttributeProgrammaticStreamSerialization;
    attr[0].val.programmaticStreamSerializationAllowed = 1;
    cfg.attrs = attr;
    cfg.numAttrs = 1;
    cudaError_t err = cudaLaunchKernelEx(&cfg, dsb_kernel, k, out);
    if (err != cudaSuccess) {
        // Fallback: plain serialized launch (still correct).
        dsb_kernel<<<COLS / 256, 256>>>(k, out);
    }
}

// round 7
// speedup vs baseline: 1.0112x; 1.0112x over previous
#include <cuda_runtime.h>
#include <cstdint>

// out[c,t,x,y] = mc ? k[t] : mp ? 0.5*k[t-1] : mn ? 0.25*k[t+1] : 0   (cases exclusive)
// Mask is channel-invariant -> precompute 2-bit selector per (t, xy) into a
// 1 MB L2-resident pair-major table sel2[h][g] (uint2, h = t/8; .x packs
// t=8h..8h+3, .y packs t=8h+4..8h+7; 4 lanes * 2 bits per t).
// Main kernel: pure 1-load/1-store rolling stream. PDL with sync at kernel
// top hides the launch gap without overlapping memory traffic into pre.

#define ALPHA 0.5f
#define BETA  0.25f

constexpr int NC = 32;
constexpr int NT = 64;
constexpr int PLANE4 = 256 * 256 / 4;     // 16384 float4 groups per t-slice
constexpr int COLS   = NC * PLANE4;       // 524288 threads in main kernel
constexpr int NPAIR  = NT / 8;            // 8 selector uint2 pairs per g

__device__ uint2 g_sel2[NPAIR * PLANE4];  // [pair h][g], 1 MB

__device__ __forceinline__ uint32_t code1(int mc, int mp, int mn) {
    return mc ? 1u : (mp ? 2u : (mn ? 3u : 0u));
}

// One thread per (pair h, g): computes 8 t-steps (t = 8h..8h+7).
// Reads mask[8h-1 .. 8h+8] (10 coalesced int4 loads), writes 1 coalesced uint2.
__global__ void __launch_bounds__(256)
pre_kernel(const int4* __restrict__ mask)
{
    const int tidg = blockIdx.x * blockDim.x + threadIdx.x;  // 0 .. NPAIR*PLANE4-1
    const int g = tidg & (PLANE4 - 1);
    const int h = tidg >> 14;            // 0..7
    const int t0 = h * 8;

    int4 mbuf[10];
    #pragma unroll
    for (int i = 0; i < 10; i++) {
        const int t = t0 - 1 + i;
        mbuf[i] = (t >= 0 && t < NT) ? __ldg(&mask[t * PLANE4 + g])
                                     : make_int4(0, 0, 0, 0);
    }

    uint32_t w[2] = {0u, 0u};
    #pragma unroll
    for (int i = 0; i < 8; i++) {
        const int4 mp = mbuf[i];
        const int4 mc = mbuf[i + 1];
        const int4 mn = mbuf[i + 2];
        uint32_t byte =  code1(mc.x, mp.x, mn.x)
                      | (code1(mc.y, mp.y, mn.y) << 2)
                      | (code1(mc.z, mp.z, mn.z) << 4)
                      | (code1(mc.w, mp.w, mn.w) << 6);
        w[i >> 2] |= byte << ((i & 3) * 8);
    }

    g_sel2[h * PLANE4 + g] = make_uint2(w[0], w[1]);   // coalesced 8B store

#if __CUDA_ARCH__ >= 900
    cudaTriggerProgrammaticLaunchCompletion();
#endif
}

__device__ __forceinline__ float pick(uint32_t c, float kc, float kp, float kn) {
    return (c == 1u) ? kc
         : (c == 2u) ? ALPHA * kp
         : (c == 3u) ? BETA * kn
         : 0.0f;
}

__global__ void __launch_bounds__(256, 8)
dsb_kernel(const float4* __restrict__ k, float4* __restrict__ out)
{
#if __CUDA_ARCH__ >= 900
    // Sync BEFORE any memory traffic: PDL only hides launch latency, no
    // contention with pre's drain.
    cudaGridDependencySynchronize();
#endif

    const int gid = blockIdx.x * blockDim.x + threadIdx.x;
    const int g = gid & (PLANE4 - 1);
    const int c = gid >> 14;

    const float4* kk = k   + (size_t)c * NT * PLANE4 + g;
    float4*       oo = out + (size_t)c * NT * PLANE4 + g;

    float4 kp = make_float4(0.f, 0.f, 0.f, 0.f);
    float4 kc = __ldcs(kk);

    int t = 0;
    #pragma unroll 1
    for (int h = 0; h < NPAIR; h++) {
        const uint2 s = __ldg(&g_sel2[h * PLANE4 + g]);   // L2-resident
        uint32_t words[2] = { s.x, s.y };
        #pragma unroll
        for (int j = 0; j < 2; j++) {
            const uint32_t wrd = words[j];
            #pragma unroll
            for (int tt = 0; tt < 4; tt++) {
                float4 kn = (t < NT - 1) ? __ldcs(kk + (t + 1) * PLANE4)
                                         : make_float4(0.f, 0.f, 0.f, 0.f);

                const uint32_t byte = (wrd >> (tt * 8)) & 0xFFu;
                float4 o;
                o.x = pick( byte       & 3u, kc.x, kp.x, kn.x);
                o.y = pick((byte >> 2) & 3u, kc.y, kp.y, kn.y);
                o.z = pick((byte >> 4) & 3u, kc.z, kp.z, kn.z);
                o.w = pick((byte >> 6) & 3u, kc.w, kp.w, kn.w);

                __stcs(oo + t * PLANE4, o);

                kp = kc; kc = kn;
                t++;
            }
        }
    }
}

extern "C" void kernel_launch(void* const* d_in, const int* in_sizes, int n_in,
                              void* d_out, int out_size)
{
    const float4* k    = (const float4*)d_in[0];
    const int4*   mask = (const int4*)d_in[1];
    float4*       out  = (float4*)d_out;

    pre_kernel<<<(NPAIR * PLANE4) / 256, 256>>>(mask);

    // PDL launch: hide dsb's launch/dispatch latency behind pre's tail.
    cudaLaunchConfig_t cfg = {};
    cfg.gridDim  = dim3(COLS / 256);
    cfg.blockDim = dim3(256);
    cfg.dynamicSmemBytes = 0;
    cfg.stream = 0;
    cudaLaunchAttribute attr[1];
    attr[0].id = cudaLaunchAttributeProgrammaticStreamSerialization;
    attr[0].val.programmaticStreamSerializationAllowed = 1;
    cfg.attrs = attr;
    cfg.numAttrs = 1;
    cudaError_t err = cudaLaunchKernelEx(&cfg, dsb_kernel, k, out);
    if (err != cudaSuccess) {
        dsb_kernel<<<COLS / 256, 256>>>(k, out);
    }
}